// round 14
// baseline (speedup 1.0000x reference)
#include <cuda_runtime.h>
#include <cuda_bf16.h>

// Problem constants
#define BB 16
#define TT 24
#define NN 2048
#define FF 64
#define BT (BB*TT)          // 384
#define NF (NN*FF)          // 131072
#define NF4 (NF/4)          // 32768 float4 per (b,t) row
#define KSPLIT 16

typedef unsigned long long u64t;

// Scratch (device globals; no allocation allowed). All fully overwritten each call.
__device__ float d_rhs[BT*NN];         // 3 MB
__device__ float d_lfp[8*BT*FF];       // lhs_f partials (8 octants per bt)
__device__ float d_Gp [KSPLIT*BT*FF];  // K-split partials of G
__device__ float d_A  [BB*TT*TT];      // attention weights

// Streaming store (evict-first): out is never re-read, keep it from evicting x.
__device__ __forceinline__ void stcs4(float4* p, float4 v) {
    asm volatile("st.global.cs.v4.f32 [%0], {%1,%2,%3,%4};"
                 :: "l"(p), "f"(v.x), "f"(v.y), "f"(v.z), "f"(v.w) : "memory");
}
__device__ __forceinline__ u64t pack2(float a) {
    u64t p;
    asm("mov.b64 %0, {%1, %1};" : "=l"(p) : "f"(a));
    return p;
}
__device__ __forceinline__ void ffma2(u64t& d, u64t a, u64t b) {
    asm("fma.rn.f32x2 %0, %1, %2, %0;" : "+l"(d) : "l"(a), "l"(b));
}
__device__ __forceinline__ void unpack2(u64t p, float& lo, float& hi) {
    asm("mov.b64 {%0, %1}, %2;" : "=f"(lo), "=f"(hi) : "l"(p));
}

// ---------------------------------------------------------------------------
// Kernel 1: single pass over ALL of x (R10 proven version).
// Each CTA (128 thr) handles one octant (256 rows) of one (b,t).
// grid = BT*8 = 3072 CTAs.
// ---------------------------------------------------------------------------
__global__ __launch_bounds__(128) void k1_pass(
    const float* __restrict__ x, const float* __restrict__ U1,
    const float* __restrict__ U3, float* __restrict__ rhs,
    float* __restrict__ lfp)
{
    const int bt   = blockIdx.x >> 3;
    const int oct  = blockIdx.x & 7;
    const int w    = threadIdx.x >> 5;
    const int lane = threadIdx.x & 31;
    const int r    = lane >> 2;
    const int q    = lane & 3;
    const float4* xb = (const float4*)(x + (size_t)bt * NF);

    float4 u3[4];
    #pragma unroll
    for (int j = 0; j < 4; j++) u3[j] = ((const float4*)U3)[q + 4*j];

    float4 acc[4];
    #pragma unroll
    for (int j = 0; j < 4; j++) acc[j] = make_float4(0.f,0.f,0.f,0.f);

    const int n0 = oct * 256 + w * 64;
    #pragma unroll 4
    for (int k = 0; k < 8; k++) {
        const int n = n0 + 8*k + r;
        const float4* row = xb + (size_t)n * 16;
        const float u1 = __ldg(U1 + n);
        float d = 0.f;
        #pragma unroll
        for (int j = 0; j < 4; j++) {
            float4 v = row[q + 4*j];
            d += v.x*u3[j].x + v.y*u3[j].y + v.z*u3[j].z + v.w*u3[j].w;
            acc[j].x += v.x*u1; acc[j].y += v.y*u1;
            acc[j].z += v.z*u1; acc[j].w += v.w*u1;
        }
        d += __shfl_down_sync(0xffffffffu, d, 2, 4);
        d += __shfl_down_sync(0xffffffffu, d, 1, 4);
        if (q == 0) rhs[bt*NN + n] = d;
    }

    #pragma unroll
    for (int off = 16; off >= 4; off >>= 1) {
        #pragma unroll
        for (int j = 0; j < 4; j++) {
            acc[j].x += __shfl_down_sync(0xffffffffu, acc[j].x, off);
            acc[j].y += __shfl_down_sync(0xffffffffu, acc[j].y, off);
            acc[j].z += __shfl_down_sync(0xffffffffu, acc[j].z, off);
            acc[j].w += __shfl_down_sync(0xffffffffu, acc[j].w, off);
        }
    }

    __shared__ float sred[4][FF];
    if (lane < 4) {
        #pragma unroll
        for (int j = 0; j < 4; j++)
            ((float4*)sred[w])[q + 4*j] = acc[j];
    }
    __syncthreads();
    if (threadIdx.x < FF) {
        float t = 0.f;
        #pragma unroll
        for (int p = 0; p < 4; p++) t += sred[p][threadIdx.x];
        lfp[(bt*8 + oct)*FF + threadIdx.x] = t;
    }
}

// ---------------------------------------------------------------------------
// Kernel 2: G = rhs(384 x 2048) @ U2(2048 x 64), K-split into 16 partials.
// ---------------------------------------------------------------------------
__global__ __launch_bounds__(128) void k2_gemm(
    const float* __restrict__ rhs, const float* __restrict__ U2,
    float* __restrict__ Gp)
{
    __shared__ float4 Us4[64*16];
    __shared__ float  Rs [32*68];
    const int m0 = blockIdx.x * 32;
    const int k0 = blockIdx.y * 128;
    const int c4 = threadIdx.x & 15;
    const int rg = threadIdx.x >> 4;

    float4 acc[4];
    #pragma unroll
    for (int r = 0; r < 4; r++) acc[r] = make_float4(0.f,0.f,0.f,0.f);

    for (int kc = 0; kc < 128; kc += 64) {
        const int kb = k0 + kc;
        __syncthreads();
        #pragma unroll
        for (int i = 0; i < 8; i++) {
            int e = threadIdx.x + i*128;
            int kk = e >> 4, cc = e & 15;
            Us4[e] = ((const float4*)(U2 + (size_t)(kb + kk)*FF))[cc];
        }
        #pragma unroll
        for (int i = 0; i < 4; i++) {
            int e = threadIdx.x + i*128;
            int row = e >> 4, kq = e & 15;
            float4 v = *(const float4*)(rhs + (size_t)(m0 + row)*NN + kb + kq*4);
            *(float4*)&Rs[row*68 + kq*4] = v;
        }
        __syncthreads();
        #pragma unroll
        for (int kk = 0; kk < 64; kk++) {
            const float4 u = Us4[kk*16 + c4];
            #pragma unroll
            for (int r = 0; r < 4; r++) {
                const float rv = Rs[(rg*4 + r)*68 + kk];
                acc[r].x += rv*u.x; acc[r].y += rv*u.y;
                acc[r].z += rv*u.z; acc[r].w += rv*u.w;
            }
        }
    }
    float* g = Gp + (size_t)blockIdx.y * (BT*FF);
    #pragma unroll
    for (int r = 0; r < 4; r++)
        *(float4*)&g[(m0 + rg*4 + r)*FF + c4*4] = acc[r];
}

// ---------------------------------------------------------------------------
// Kernel 3: per batch: product -> sigmoid(+be) -> E -> softmax (8 lfp partials).
// ---------------------------------------------------------------------------
__global__ __launch_bounds__(576) void k3_scores(
    const float* __restrict__ lfp, const float* __restrict__ Gp,
    const float* __restrict__ be, const float* __restrict__ Ve,
    float* __restrict__ A)
{
    const int b = blockIdx.x;
    __shared__ float lfs[TT*65], Gs[TT*65], sg[TT*25], Em[TT*25];
    __shared__ float cmax[TT], csum[TT];
    const int tid = threadIdx.x;

    for (int e = tid; e < TT*FF; e += 576) {
        int t = e >> 6, f = e & 63;
        const int bt = b*TT + t;
        float lv = 0.f;
        #pragma unroll
        for (int p = 0; p < 8; p++) lv += lfp[(bt*8 + p)*FF + f];
        lfs[t*65 + f] = lv;
        float g = 0.f;
        #pragma unroll
        for (int ks = 0; ks < KSPLIT; ks++)
            g += Gp[(size_t)ks*(BT*FF) + bt*FF + f];
        Gs[t*65 + f] = g;
    }
    __syncthreads();

    const int t = tid / TT;
    const int s = tid % TT;
    float p = 0.f;
    #pragma unroll
    for (int f = 0; f < FF; f++)
        p += lfs[t*65 + f] * Gs[s*65 + f];
    sg[t*25 + s] = 1.f / (1.f + __expf(-(p + be[t*TT + s])));
    __syncthreads();

    float e = 0.f;
    #pragma unroll
    for (int s2 = 0; s2 < TT; s2++)
        e += Ve[t*TT + s2] * sg[s2*25 + s];
    Em[t*25 + s] = e;
    __syncthreads();

    if (t == 0) {
        float m = -1e30f;
        #pragma unroll
        for (int tt2 = 0; tt2 < TT; tt2++) m = fmaxf(m, Em[tt2*25 + s]);
        cmax[s] = m;
    }
    __syncthreads();
    const float ex = __expf(Em[t*25 + s] - cmax[s]);
    Em[t*25 + s] = ex;
    __syncthreads();
    if (t == 0) {
        float sm = 0.f;
        #pragma unroll
        for (int tt2 = 0; tt2 < TT; tt2++) sm += Em[tt2*25 + s];
        csum[s] = sm;
    }
    __syncthreads();
    A[b*TT*TT + t*TT + s] = ex / csum[s];
}

// ---------------------------------------------------------------------------
// Kernel 4: out[b,s,nf] = sum_t x[b,t,nf] * A[b,t,s], t-outer + f32x2.
// Accumulators live as packed s-pairs: acc[sp][e] = (out[2sp][e], out[2sp+1][e])
// (48 u64 = 96 regs). Per t: 1 LDG.128 (x streamed, read once) + 4 dup-movs +
// per sp: 1 LDS.64 of the CONTIGUOUS A-pair (no duplication -> same L1 bytes
// as R10) + 4 FFMA2. Issue -33%, fma-pipe instrs halved. .cs stores kept.
// ---------------------------------------------------------------------------
__global__ __launch_bounds__(128, 4) void k4_out(
    const float4* __restrict__ x4, const float* __restrict__ A,
    float4* __restrict__ out4)
{
    __shared__ float2 As2[TT*12];   // [t][sp] = (A[t,2sp], A[t,2sp+1])
    const int b = (BB - 1) - blockIdx.y;   // reverse batch order for L2 reuse
    const float2* Ab2 = (const float2*)(A + b*TT*TT);
    for (int i = threadIdx.x; i < TT*12; i += 128)
        As2[i] = Ab2[i];
    __syncthreads();

    const size_t c = (size_t)blockIdx.x * 128 + threadIdx.x;  // float4 column
    const float4* xb = x4 + (size_t)b * TT * NF4 + c;

    u64t acc[12][4];
    #pragma unroll
    for (int sp = 0; sp < 12; sp++)
        #pragma unroll
        for (int e = 0; e < 4; e++) acc[sp][e] = 0ull;

    #pragma unroll 4
    for (int t = 0; t < TT; t++) {
        const float4 v = xb[(size_t)t * NF4];
        const u64t vx = pack2(v.x), vy = pack2(v.y);
        const u64t vz = pack2(v.z), vw = pack2(v.w);
        #pragma unroll
        for (int sp = 0; sp < 12; sp++) {
            const u64t aa = *(const u64t*)&As2[t*12 + sp];
            ffma2(acc[sp][0], vx, aa);
            ffma2(acc[sp][1], vy, aa);
            ffma2(acc[sp][2], vz, aa);
            ffma2(acc[sp][3], vw, aa);
        }
    }

    float4* ob = out4 + (size_t)b * TT * NF4 + c;
    #pragma unroll
    for (int sp = 0; sp < 12; sp++) {
        float4 o0, o1;
        unpack2(acc[sp][0], o0.x, o1.x);
        unpack2(acc[sp][1], o0.y, o1.y);
        unpack2(acc[sp][2], o0.z, o1.z);
        unpack2(acc[sp][3], o0.w, o1.w);
        stcs4(ob + (size_t)(2*sp    ) * NF4, o0);
        stcs4(ob + (size_t)(2*sp + 1) * NF4, o1);
    }
}

// ---------------------------------------------------------------------------
extern "C" void kernel_launch(void* const* d_in, const int* in_sizes, int n_in,
                              void* d_out, int out_size)
{
    const float* x  = (const float*)d_in[0];
    const float* U1 = (const float*)d_in[1];
    const float* U2 = (const float*)d_in[2];
    const float* U3 = (const float*)d_in[3];
    const float* be = (const float*)d_in[4];
    const float* Ve = (const float*)d_in[5];

    float *rhs, *lfp, *Gp, *A;
    cudaGetSymbolAddress((void**)&rhs, d_rhs);
    cudaGetSymbolAddress((void**)&lfp, d_lfp);
    cudaGetSymbolAddress((void**)&Gp,  d_Gp);
    cudaGetSymbolAddress((void**)&A,   d_A);

    k1_pass<<<BT*8, 128>>>(x, U1, U3, rhs, lfp);
    k2_gemm<<<dim3(BT/32, KSPLIT), 128>>>(rhs, U2, Gp);
    k3_scores<<<BB, 576>>>(lfp, Gp, be, Ve, A);
    k4_out<<<dim3(NF4/128, BB), 128>>>((const float4*)x, A, (float4*)d_out);
}

// round 15
// speedup vs baseline: 1.3722x; 1.3722x over previous
#include <cuda_runtime.h>
#include <cuda_bf16.h>

// Problem constants
#define BB 16
#define TT 24
#define NN 2048
#define FF 64
#define BT (BB*TT)          // 384
#define NF (NN*FF)          // 131072
#define NF4 (NF/4)          // 32768 float4 per (b,t) row
#define KSPLIT 16

// Scratch (device globals; no allocation allowed). All fully overwritten each call.
__device__ float d_rhs[BT*NN];         // 3 MB
__device__ float d_lfp[8*BT*FF];       // lhs_f partials (8 octants per bt)
__device__ float d_Gp [KSPLIT*BT*FF];  // K-split partials of G
__device__ float d_A  [BB*TT*TT];      // attention weights

// Streaming store (evict-first): out is never re-read, keep it from evicting x.
__device__ __forceinline__ void stcs4(float4* p, float4 v) {
    asm volatile("st.global.cs.v4.f32 [%0], {%1,%2,%3,%4};"
                 :: "l"(p), "f"(v.x), "f"(v.y), "f"(v.z), "f"(v.w) : "memory");
}

// ---------------------------------------------------------------------------
// Kernel 1: single pass over ALL of x.
// Each CTA (128 thr) handles one octant (256 rows) of one (b,t).
// grid = BT*8 = 3072 CTAs. FULL unroll of the 8 row-iterations + U1 preload
// so all 32 LDG.128 are independent and batchable (MLP ~32).
// ---------------------------------------------------------------------------
__global__ __launch_bounds__(128) void k1_pass(
    const float* __restrict__ x, const float* __restrict__ U1,
    const float* __restrict__ U3, float* __restrict__ rhs,
    float* __restrict__ lfp)
{
    const int bt   = blockIdx.x >> 3;
    const int oct  = blockIdx.x & 7;
    const int w    = threadIdx.x >> 5;
    const int lane = threadIdx.x & 31;
    const int r    = lane >> 2;
    const int q    = lane & 3;
    const float4* xb = (const float4*)(x + (size_t)bt * NF);

    float4 u3[4];
    #pragma unroll
    for (int j = 0; j < 4; j++) u3[j] = ((const float4*)U3)[q + 4*j];

    const int n0 = oct * 256 + w * 64;

    // preload the 8 U1 values this lane's rows need (independent LDG.32)
    float u1v[8];
    #pragma unroll
    for (int k = 0; k < 8; k++) u1v[k] = __ldg(U1 + n0 + 8*k + r);

    float4 acc[4];
    #pragma unroll
    for (int j = 0; j < 4; j++) acc[j] = make_float4(0.f,0.f,0.f,0.f);

    #pragma unroll
    for (int k = 0; k < 8; k++) {
        const int n = n0 + 8*k + r;
        const float4* row = xb + (size_t)n * 16;
        const float u1 = u1v[k];
        float d = 0.f;
        #pragma unroll
        for (int j = 0; j < 4; j++) {
            float4 v = row[q + 4*j];
            d += v.x*u3[j].x + v.y*u3[j].y + v.z*u3[j].z + v.w*u3[j].w;
            acc[j].x += v.x*u1; acc[j].y += v.y*u1;
            acc[j].z += v.z*u1; acc[j].w += v.w*u1;
        }
        d += __shfl_down_sync(0xffffffffu, d, 2, 4);
        d += __shfl_down_sync(0xffffffffu, d, 1, 4);
        if (q == 0) rhs[bt*NN + n] = d;
    }

    #pragma unroll
    for (int off = 16; off >= 4; off >>= 1) {
        #pragma unroll
        for (int j = 0; j < 4; j++) {
            acc[j].x += __shfl_down_sync(0xffffffffu, acc[j].x, off);
            acc[j].y += __shfl_down_sync(0xffffffffu, acc[j].y, off);
            acc[j].z += __shfl_down_sync(0xffffffffu, acc[j].z, off);
            acc[j].w += __shfl_down_sync(0xffffffffu, acc[j].w, off);
        }
    }

    __shared__ float sred[4][FF];
    if (lane < 4) {
        #pragma unroll
        for (int j = 0; j < 4; j++)
            ((float4*)sred[w])[q + 4*j] = acc[j];
    }
    __syncthreads();
    if (threadIdx.x < FF) {
        float t = 0.f;
        #pragma unroll
        for (int p = 0; p < 4; p++) t += sred[p][threadIdx.x];
        lfp[(bt*8 + oct)*FF + threadIdx.x] = t;
    }
}

// ---------------------------------------------------------------------------
// Kernel 2: G = rhs(384 x 2048) @ U2(2048 x 64), K-split into 16 partials.
// ---------------------------------------------------------------------------
__global__ __launch_bounds__(128) void k2_gemm(
    const float* __restrict__ rhs, const float* __restrict__ U2,
    float* __restrict__ Gp)
{
    __shared__ float4 Us4[64*16];
    __shared__ float  Rs [32*68];
    const int m0 = blockIdx.x * 32;
    const int k0 = blockIdx.y * 128;
    const int c4 = threadIdx.x & 15;
    const int rg = threadIdx.x >> 4;

    float4 acc[4];
    #pragma unroll
    for (int r = 0; r < 4; r++) acc[r] = make_float4(0.f,0.f,0.f,0.f);

    for (int kc = 0; kc < 128; kc += 64) {
        const int kb = k0 + kc;
        __syncthreads();
        #pragma unroll
        for (int i = 0; i < 8; i++) {
            int e = threadIdx.x + i*128;
            int kk = e >> 4, cc = e & 15;
            Us4[e] = ((const float4*)(U2 + (size_t)(kb + kk)*FF))[cc];
        }
        #pragma unroll
        for (int i = 0; i < 4; i++) {
            int e = threadIdx.x + i*128;
            int row = e >> 4, kq = e & 15;
            float4 v = *(const float4*)(rhs + (size_t)(m0 + row)*NN + kb + kq*4);
            *(float4*)&Rs[row*68 + kq*4] = v;
        }
        __syncthreads();
        #pragma unroll
        for (int kk = 0; kk < 64; kk++) {
            const float4 u = Us4[kk*16 + c4];
            #pragma unroll
            for (int r = 0; r < 4; r++) {
                const float rv = Rs[(rg*4 + r)*68 + kk];
                acc[r].x += rv*u.x; acc[r].y += rv*u.y;
                acc[r].z += rv*u.z; acc[r].w += rv*u.w;
            }
        }
    }
    float* g = Gp + (size_t)blockIdx.y * (BT*FF);
    #pragma unroll
    for (int r = 0; r < 4; r++)
        *(float4*)&g[(m0 + rg*4 + r)*FF + c4*4] = acc[r];
}

// ---------------------------------------------------------------------------
// Kernel 3: per batch: product -> sigmoid(+be) -> E -> softmax (8 lfp partials).
// ---------------------------------------------------------------------------
__global__ __launch_bounds__(576) void k3_scores(
    const float* __restrict__ lfp, const float* __restrict__ Gp,
    const float* __restrict__ be, const float* __restrict__ Ve,
    float* __restrict__ A)
{
    const int b = blockIdx.x;
    __shared__ float lfs[TT*65], Gs[TT*65], sg[TT*25], Em[TT*25];
    __shared__ float cmax[TT], csum[TT];
    const int tid = threadIdx.x;

    for (int e = tid; e < TT*FF; e += 576) {
        int t = e >> 6, f = e & 63;
        const int bt = b*TT + t;
        float lv = 0.f;
        #pragma unroll
        for (int p = 0; p < 8; p++) lv += lfp[(bt*8 + p)*FF + f];
        lfs[t*65 + f] = lv;
        float g = 0.f;
        #pragma unroll
        for (int ks = 0; ks < KSPLIT; ks++)
            g += Gp[(size_t)ks*(BT*FF) + bt*FF + f];
        Gs[t*65 + f] = g;
    }
    __syncthreads();

    const int t = tid / TT;
    const int s = tid % TT;
    float p = 0.f;
    #pragma unroll
    for (int f = 0; f < FF; f++)
        p += lfs[t*65 + f] * Gs[s*65 + f];
    sg[t*25 + s] = 1.f / (1.f + __expf(-(p + be[t*TT + s])));
    __syncthreads();

    float e = 0.f;
    #pragma unroll
    for (int s2 = 0; s2 < TT; s2++)
        e += Ve[t*TT + s2] * sg[s2*25 + s];
    Em[t*25 + s] = e;
    __syncthreads();

    if (t == 0) {
        float m = -1e30f;
        #pragma unroll
        for (int tt2 = 0; tt2 < TT; tt2++) m = fmaxf(m, Em[tt2*25 + s]);
        cmax[s] = m;
    }
    __syncthreads();
    const float ex = __expf(Em[t*25 + s] - cmax[s]);
    Em[t*25 + s] = ex;
    __syncthreads();
    if (t == 0) {
        float sm = 0.f;
        #pragma unroll
        for (int tt2 = 0; tt2 < TT; tt2++) sm += Em[tt2*25 + s];
        csum[s] = sm;
    }
    __syncthreads();
    A[b*TT*TT + t*TT + s] = ex / csum[s];
}

// ---------------------------------------------------------------------------
// Kernel 4 (FROZEN at R13 best): out[b,s,nf] = sum_t x[b,t,nf] * A[b,t,s].
// float4 column per thread (xr = 24 x float4), s in pairs, A as float2 in
// smem, 4 CTAs/SM, reverse batch order, .cs streaming stores.
// ---------------------------------------------------------------------------
__global__ __launch_bounds__(128, 4) void k4_out(
    const float4* __restrict__ x4, const float* __restrict__ A,
    float4* __restrict__ out4)
{
    __shared__ float2 As2[TT*12];
    const int b = (BB - 1) - blockIdx.y;
    const float2* Ab2 = (const float2*)(A + b*TT*TT);
    for (int i = threadIdx.x; i < TT*12; i += 128)
        As2[i] = Ab2[i];
    __syncthreads();

    const size_t c = (size_t)blockIdx.x * 128 + threadIdx.x;
    const float4* xb = x4 + (size_t)b * TT * NF4 + c;

    float4 xr[TT];
    #pragma unroll
    for (int t = 0; t < TT; t++) xr[t] = xb[(size_t)t * NF4];

    float4* ob = out4 + (size_t)b * TT * NF4 + c;
    #pragma unroll 1
    for (int sp = 0; sp < 12; sp++) {
        float4 a0 = make_float4(0.f,0.f,0.f,0.f);
        float4 a1 = make_float4(0.f,0.f,0.f,0.f);
        #pragma unroll
        for (int t = 0; t < TT; t++) {
            const float2 av = As2[t*12 + sp];
            a0.x += xr[t].x*av.x; a0.y += xr[t].y*av.x; a0.z += xr[t].z*av.x; a0.w += xr[t].w*av.x;
            a1.x += xr[t].x*av.y; a1.y += xr[t].y*av.y; a1.z += xr[t].z*av.y; a1.w += xr[t].w*av.y;
        }
        stcs4(ob + (size_t)(2*sp    ) * NF4, a0);
        stcs4(ob + (size_t)(2*sp + 1) * NF4, a1);
    }
}

// ---------------------------------------------------------------------------
extern "C" void kernel_launch(void* const* d_in, const int* in_sizes, int n_in,
                              void* d_out, int out_size)
{
    const float* x  = (const float*)d_in[0];
    const float* U1 = (const float*)d_in[1];
    const float* U2 = (const float*)d_in[2];
    const float* U3 = (const float*)d_in[3];
    const float* be = (const float*)d_in[4];
    const float* Ve = (const float*)d_in[5];

    float *rhs, *lfp, *Gp, *A;
    cudaGetSymbolAddress((void**)&rhs, d_rhs);
    cudaGetSymbolAddress((void**)&lfp, d_lfp);
    cudaGetSymbolAddress((void**)&Gp,  d_Gp);
    cudaGetSymbolAddress((void**)&A,   d_A);

    k1_pass<<<BT*8, 128>>>(x, U1, U3, rhs, lfp);
    k2_gemm<<<dim3(BT/32, KSPLIT), 128>>>(rhs, U2, Gp);
    k3_scores<<<BB, 576>>>(lfp, Gp, be, Ve, A);
    k4_out<<<dim3(NF4/128, BB), 128>>>((const float4*)x, A, (float4*)d_out);
}